// round 1
// baseline (speedup 1.0000x reference)
#include <cuda_runtime.h>
#include <cuda_bf16.h>
#include <math.h>

// Problem constants
#define S_LEN 64
#define T_LEN 48
#define BATCH 32
#define VOCAB 32000
#define EDIM 512
#define HDIM 512
#define G3H (3 * HDIM)       // 1536
#define ENC_TOK (S_LEN * BATCH)      // 2048
#define DEC_TOK ((T_LEN - 1) * BATCH) // 1504

// ---------------------------------------------------------------------------
// Scratch (device globals; no runtime allocation allowed)
// ---------------------------------------------------------------------------
__device__ float g_x[ENC_TOK * EDIM];      // embeddings / layer inputs (4 MB)
__device__ float g_gi[ENC_TOK * G3H];      // precomputed input gates (12.6 MB)
__device__ float g_seq0[ENC_TOK * HDIM];   // layer outputs ping
__device__ float g_seq1[ENC_TOK * HDIM];   // layer outputs pong
__device__ float g_hA0[BATCH * HDIM];
__device__ float g_hB0[BATCH * HDIM];
__device__ float g_hA1[BATCH * HDIM];
__device__ float g_hB1[BATCH * HDIM];

// ---------------------------------------------------------------------------
// Embedding gather: out[t, :] = emb[idx[t], :]
// grid = ntok blocks, block = 128 threads (one float4 each, E=512)
// ---------------------------------------------------------------------------
__global__ void embed_kernel(const int* __restrict__ idx,
                             const float* __restrict__ emb,
                             float* __restrict__ out, int ntok) {
    int t = blockIdx.x;
    if (t >= ntok) return;
    int token = idx[t];
    const float4* src = (const float4*)(emb + (size_t)token * EDIM);
    float4* dst = (float4*)(out + (size_t)t * EDIM);
    dst[threadIdx.x] = src[threadIdx.x];
}

__global__ void zero_kernel(float* __restrict__ p, int n) {
    int i = blockIdx.x * blockDim.x + threadIdx.x;
    if (i < n) p[i] = 0.0f;
}

// ---------------------------------------------------------------------------
// C[M,N] = A[M,K] @ W[N,K]^T + bias[N]
// Classic 128x128x8 SMEM-tiled fp32 GEMM, 256 threads, 8x8 microtile.
// Requires: N % 128 == 0, K % 8 == 0. M guarded.
// ---------------------------------------------------------------------------
__global__ void __launch_bounds__(256)
sgemm_bias(const float* __restrict__ A, const float* __restrict__ W,
           const float* __restrict__ bias, float* __restrict__ C,
           int M, int N, int K) {
    const int BM = 128, BN = 128, BK = 8;
    __shared__ float As[BK][BM];
    __shared__ float Bs[BK][BN];

    int bm = blockIdx.y * BM;
    int bn = blockIdx.x * BN;
    int tid = threadIdx.x;

    int lrow = tid >> 1;          // 0..127
    int lcol4 = (tid & 1) * 4;    // 0 or 4

    int tx = tid & 15;            // 0..15 -> N microtile
    int ty = tid >> 4;            // 0..15 -> M microtile

    float acc[8][8];
#pragma unroll
    for (int i = 0; i < 8; i++)
#pragma unroll
        for (int j = 0; j < 8; j++) acc[i][j] = 0.0f;

    for (int k0 = 0; k0 < K; k0 += BK) {
        // Load A tile (transposed into SMEM), guard M
        float4 av = make_float4(0.f, 0.f, 0.f, 0.f);
        if (bm + lrow < M)
            av = *(const float4*)(A + (size_t)(bm + lrow) * K + k0 + lcol4);
        As[lcol4 + 0][lrow] = av.x;
        As[lcol4 + 1][lrow] = av.y;
        As[lcol4 + 2][lrow] = av.z;
        As[lcol4 + 3][lrow] = av.w;
        // Load W tile (N rows, K-contiguous) -> Bs[k][n]; N is always mult of 128
        float4 bv = *(const float4*)(W + (size_t)(bn + lrow) * K + k0 + lcol4);
        Bs[lcol4 + 0][lrow] = bv.x;
        Bs[lcol4 + 1][lrow] = bv.y;
        Bs[lcol4 + 2][lrow] = bv.z;
        Bs[lcol4 + 3][lrow] = bv.w;
        __syncthreads();

#pragma unroll
        for (int k = 0; k < BK; k++) {
            float4 a0 = *(const float4*)&As[k][ty * 8];
            float4 a1 = *(const float4*)&As[k][ty * 8 + 4];
            float4 b0 = *(const float4*)&Bs[k][tx * 8];
            float4 b1 = *(const float4*)&Bs[k][tx * 8 + 4];
            float ar[8] = {a0.x, a0.y, a0.z, a0.w, a1.x, a1.y, a1.z, a1.w};
            float br[8] = {b0.x, b0.y, b0.z, b0.w, b1.x, b1.y, b1.z, b1.w};
#pragma unroll
            for (int i = 0; i < 8; i++)
#pragma unroll
                for (int j = 0; j < 8; j++) acc[i][j] += ar[i] * br[j];
        }
        __syncthreads();
    }

    // Epilogue: add bias, store (M guarded, float4 stores)
    int ncol = bn + tx * 8;
    float4 bb0 = *(const float4*)(bias + ncol);
    float4 bb1 = *(const float4*)(bias + ncol + 4);
#pragma unroll
    for (int i = 0; i < 8; i++) {
        int m = bm + ty * 8 + i;
        if (m >= M) continue;
        float* crow = C + (size_t)m * N + ncol;
        float4 v0 = make_float4(acc[i][0] + bb0.x, acc[i][1] + bb0.y,
                                acc[i][2] + bb0.z, acc[i][3] + bb0.w);
        float4 v1 = make_float4(acc[i][4] + bb1.x, acc[i][5] + bb1.y,
                                acc[i][6] + bb1.z, acc[i][7] + bb1.w);
        *(float4*)(crow) = v0;
        *(float4*)(crow + 4) = v1;
    }
}

// ---------------------------------------------------------------------------
// One GRU timestep (PyTorch convention), fused gh GEMM + gates.
//   gi: [B, 3H] precomputed input gates for this timestep (ir | iz | in)
//   h_in: [B, H], Whh: [3H, H], bhh: [3H]
//   h_out, y_out: [B, H]
// grid = (H/8, 2); block = 128 threads.
//   thread: b = by*16 + tid%16, n = bx*8 + tid/16
// Each block stages 16 h rows x 64 K-chunk and 24 Whh rows x 64 through SMEM.
// ---------------------------------------------------------------------------
__global__ void __launch_bounds__(128)
gru_step(const float* __restrict__ gi, const float* __restrict__ h_in,
         const float* __restrict__ Whh, const float* __restrict__ bhh,
         float* __restrict__ h_out, float* __restrict__ y_out) {
    const int KC = 64;
    __shared__ float hs[16][KC + 1];
    __shared__ float ws[24][KC + 1];

    int tid = threadIdx.x;
    int bl = tid & 15;     // batch local 0..15
    int nl = tid >> 4;     // 0..7
    int b = blockIdx.y * 16 + bl;
    int n0 = blockIdx.x * 8;
    int n = n0 + nl;

    float accr = 0.f, accz = 0.f, accn = 0.f;

    for (int k0 = 0; k0 < HDIM; k0 += KC) {
        __syncthreads();
        // stage h chunk: 16 rows x 64
        for (int i = tid; i < 16 * KC; i += 128) {
            int r = i >> 6, c = i & 63;
            hs[r][c] = h_in[(blockIdx.y * 16 + r) * HDIM + k0 + c];
        }
        // stage Whh chunk: 3 gates x 8 rows x 64
        for (int i = tid; i < 24 * KC; i += 128) {
            int r = i >> 6, c = i & 63;
            int gate = r >> 3, nn = r & 7;
            ws[r][c] = Whh[(size_t)(gate * HDIM + n0 + nn) * HDIM + k0 + c];
        }
        __syncthreads();
#pragma unroll 16
        for (int k = 0; k < KC; k++) {
            float hv = hs[bl][k];
            accr += hv * ws[nl][k];
            accz += hv * ws[8 + nl][k];
            accn += hv * ws[16 + nl][k];
        }
    }

    const float* girow = gi + (size_t)b * G3H;
    float ir = girow[n];
    float iz = girow[HDIM + n];
    float inn = girow[2 * HDIM + n];
    float hr = accr + bhh[n];
    float hz = accz + bhh[HDIM + n];
    float hn = accn + bhh[2 * HDIM + n];

    float r = 1.0f / (1.0f + expf(-(ir + hr)));
    float z = 1.0f / (1.0f + expf(-(iz + hz)));
    float cand = tanhf(inn + r * hn);
    float hprev = h_in[(size_t)b * HDIM + n];
    float hnew = (1.0f - z) * cand + z * hprev;

    h_out[(size_t)b * HDIM + n] = hnew;
    y_out[(size_t)b * HDIM + n] = hnew;
}

// ---------------------------------------------------------------------------
// Host orchestration
// ---------------------------------------------------------------------------
extern "C" void kernel_launch(void* const* d_in, const int* in_sizes, int n_in,
                              void* d_out, int out_size) {
    const int*   src      = (const int*)d_in[0];
    const int*   trg      = (const int*)d_in[1];
    const float* enc_emb  = (const float*)d_in[2];
    const float* enc_Wih0 = (const float*)d_in[3];
    const float* enc_Whh0 = (const float*)d_in[4];
    const float* enc_bih0 = (const float*)d_in[5];
    const float* enc_bhh0 = (const float*)d_in[6];
    const float* enc_Wih1 = (const float*)d_in[7];
    const float* enc_Whh1 = (const float*)d_in[8];
    const float* enc_bih1 = (const float*)d_in[9];
    const float* enc_bhh1 = (const float*)d_in[10];
    const float* dec_emb  = (const float*)d_in[11];
    const float* dec_Wih0 = (const float*)d_in[12];
    const float* dec_Whh0 = (const float*)d_in[13];
    const float* dec_bih0 = (const float*)d_in[14];
    const float* dec_bhh0 = (const float*)d_in[15];
    const float* dec_Wih1 = (const float*)d_in[16];
    const float* dec_Whh1 = (const float*)d_in[17];
    const float* dec_bih1 = (const float*)d_in[18];
    const float* dec_bhh1 = (const float*)d_in[19];
    const float* out_W    = (const float*)d_in[20];
    const float* out_b    = (const float*)d_in[21];
    float* out = (float*)d_out;

    float *x, *gi, *seq0, *seq1, *hA0, *hB0, *hA1, *hB1;
    cudaGetSymbolAddress((void**)&x,    g_x);
    cudaGetSymbolAddress((void**)&gi,   g_gi);
    cudaGetSymbolAddress((void**)&seq0, g_seq0);
    cudaGetSymbolAddress((void**)&seq1, g_seq1);
    cudaGetSymbolAddress((void**)&hA0,  g_hA0);
    cudaGetSymbolAddress((void**)&hB0,  g_hB0);
    cudaGetSymbolAddress((void**)&hA1,  g_hA1);
    cudaGetSymbolAddress((void**)&hB1,  g_hB1);

    const int HB = BATCH * HDIM; // 16384
    dim3 stepGrid(HDIM / 8, 2);

    // ---- Encoder ----
    embed_kernel<<<ENC_TOK, 128>>>(src, enc_emb, x, ENC_TOK);
    zero_kernel<<<(HB + 255) / 256, 256>>>(hA0, HB);
    zero_kernel<<<(HB + 255) / 256, 256>>>(hA1, HB);

    // enc layer 0: gi = x @ Wih0^T + bih0  (2048 x 1536 x 512)
    sgemm_bias<<<dim3(G3H / 128, (ENC_TOK + 127) / 128), 256>>>(
        x, enc_Wih0, enc_bih0, gi, ENC_TOK, G3H, EDIM);
    {
        float* hin = hA0; float* hout = hB0;
        for (int t = 0; t < S_LEN; t++) {
            gru_step<<<stepGrid, 128>>>(gi + (size_t)t * BATCH * G3H, hin,
                                        enc_Whh0, enc_bhh0, hout,
                                        seq0 + (size_t)t * BATCH * HDIM);
            float* tmp = hin; hin = hout; hout = tmp;
        }
        // after 64 steps final state is back in hA0
    }

    // enc layer 1: gi = seq0 @ Wih1^T + bih1
    sgemm_bias<<<dim3(G3H / 128, (ENC_TOK + 127) / 128), 256>>>(
        seq0, enc_Wih1, enc_bih1, gi, ENC_TOK, G3H, HDIM);
    {
        float* hin = hA1; float* hout = hB1;
        for (int t = 0; t < S_LEN; t++) {
            gru_step<<<stepGrid, 128>>>(gi + (size_t)t * BATCH * G3H, hin,
                                        enc_Whh1, enc_bhh1, hout,
                                        seq1 + (size_t)t * BATCH * HDIM);
            float* tmp = hin; hin = hout; hout = tmp;
        }
        // final enc layer-1 state in hA1
    }

    // ---- Decoder ----
    // dec embeddings: trg[:-1] = first 1504 tokens of trg
    embed_kernel<<<DEC_TOK, 128>>>(trg, dec_emb, x, DEC_TOK);

    // dec layer 0 (init = enc layer0 final state, currently in hA0)
    sgemm_bias<<<dim3(G3H / 128, (DEC_TOK + 127) / 128), 256>>>(
        x, dec_Wih0, dec_bih0, gi, DEC_TOK, G3H, EDIM);
    {
        float* hin = hA0; float* hout = hB0;
        for (int t = 0; t < T_LEN - 1; t++) {
            gru_step<<<stepGrid, 128>>>(gi + (size_t)t * BATCH * G3H, hin,
                                        dec_Whh0, dec_bhh0, hout,
                                        seq0 + (size_t)t * BATCH * HDIM);
            float* tmp = hin; hin = hout; hout = tmp;
        }
    }

    // dec layer 1 (init = enc layer1 final state, currently in hA1)
    sgemm_bias<<<dim3(G3H / 128, (DEC_TOK + 127) / 128), 256>>>(
        seq0, dec_Wih1, dec_bih1, gi, DEC_TOK, G3H, HDIM);
    {
        float* hin = hA1; float* hout = hB1;
        for (int t = 0; t < T_LEN - 1; t++) {
            gru_step<<<stepGrid, 128>>>(gi + (size_t)t * BATCH * G3H, hin,
                                        dec_Whh1, dec_bhh1, hout,
                                        seq1 + (size_t)t * BATCH * HDIM);
            float* tmp = hin; hin = hout; hout = tmp;
        }
    }

    // ---- Output projection: logits = seq1 @ out_W^T + out_b ----
    sgemm_bias<<<dim3(VOCAB / 128, (DEC_TOK + 127) / 128), 256>>>(
        seq1, out_W, out_b, out, DEC_TOK, VOCAB, HDIM);
}

// round 2
// speedup vs baseline: 2.4483x; 2.4483x over previous
#include <cuda_runtime.h>
#include <cuda_bf16.h>
#include <math.h>

// Problem constants
#define S_LEN 64
#define T_LEN 48
#define BATCH 32
#define VOCAB 32000
#define EDIM 512
#define HDIM 512
#define G3H (3 * HDIM)                 // 1536
#define ENC_TOK (S_LEN * BATCH)        // 2048
#define DEC_TOK ((T_LEN - 1) * BATCH)  // 1504

#define NBLOCKS_GRU 128

// ---------------------------------------------------------------------------
// Scratch (device globals; no runtime allocation allowed)
// ---------------------------------------------------------------------------
__device__ float g_x[ENC_TOK * EDIM];
__device__ float g_gi[ENC_TOK * G3H];
__device__ float g_seq0[ENC_TOK * HDIM];
__device__ float g_seq1[ENC_TOK * HDIM];
__device__ float g_hA0[BATCH * HDIM];
__device__ float g_hB0[BATCH * HDIM];
__device__ float g_hA1[BATCH * HDIM];
__device__ float g_hB1[BATCH * HDIM];

// software grid barrier state (monotonic generation; returns to count=0 after
// every barrier, so state is consistent across graph replays)
__device__ unsigned int g_bar_count = 0;
__device__ unsigned int g_bar_gen = 0;

// ---------------------------------------------------------------------------
__global__ void embed_kernel(const int* __restrict__ idx,
                             const float* __restrict__ emb,
                             float* __restrict__ out, int ntok) {
    int t = blockIdx.x;
    if (t >= ntok) return;
    int token = idx[t];
    const float4* src = (const float4*)(emb + (size_t)token * EDIM);
    float4* dst = (float4*)(out + (size_t)t * EDIM);
    dst[threadIdx.x] = src[threadIdx.x];
}

__global__ void zero_kernel(float* __restrict__ p, int n) {
    int i = blockIdx.x * blockDim.x + threadIdx.x;
    if (i < n) p[i] = 0.0f;
}

// ---------------------------------------------------------------------------
// C[M,N] = A[M,K] @ W[N,K]^T + bias[N]
// 128x128x16 SMEM-tiled fp32 GEMM, 256 threads, 8x8 microtile.
// Requires: N % 128 == 0, K % 16 == 0. M guarded.
// ---------------------------------------------------------------------------
__global__ void __launch_bounds__(256)
sgemm_bias(const float* __restrict__ A, const float* __restrict__ W,
           const float* __restrict__ bias, float* __restrict__ C,
           int M, int N, int K) {
    const int BM = 128, BN = 128, BK = 16;
    __shared__ float As[BK][BM];
    __shared__ float Bs[BK][BN];

    int bm = blockIdx.y * BM;
    int bn = blockIdx.x * BN;
    int tid = threadIdx.x;

    int lrow = tid >> 1;        // 0..127
    int lk = (tid & 1) * 8;     // 0 or 8

    int tx = tid & 15;          // N microtile
    int ty = tid >> 4;          // M microtile

    float acc[8][8];
#pragma unroll
    for (int i = 0; i < 8; i++)
#pragma unroll
        for (int j = 0; j < 8; j++) acc[i][j] = 0.0f;

    for (int k0 = 0; k0 < K; k0 += BK) {
        float4 av0 = make_float4(0.f, 0.f, 0.f, 0.f);
        float4 av1 = make_float4(0.f, 0.f, 0.f, 0.f);
        if (bm + lrow < M) {
            const float* ap = A + (size_t)(bm + lrow) * K + k0 + lk;
            av0 = *(const float4*)(ap);
            av1 = *(const float4*)(ap + 4);
        }
        As[lk + 0][lrow] = av0.x; As[lk + 1][lrow] = av0.y;
        As[lk + 2][lrow] = av0.z; As[lk + 3][lrow] = av0.w;
        As[lk + 4][lrow] = av1.x; As[lk + 5][lrow] = av1.y;
        As[lk + 6][lrow] = av1.z; As[lk + 7][lrow] = av1.w;

        const float* wp = W + (size_t)(bn + lrow) * K + k0 + lk;
        float4 bv0 = *(const float4*)(wp);
        float4 bv1 = *(const float4*)(wp + 4);
        Bs[lk + 0][lrow] = bv0.x; Bs[lk + 1][lrow] = bv0.y;
        Bs[lk + 2][lrow] = bv0.z; Bs[lk + 3][lrow] = bv0.w;
        Bs[lk + 4][lrow] = bv1.x; Bs[lk + 5][lrow] = bv1.y;
        Bs[lk + 6][lrow] = bv1.z; Bs[lk + 7][lrow] = bv1.w;
        __syncthreads();

#pragma unroll
        for (int k = 0; k < BK; k++) {
            float4 a0 = *(const float4*)&As[k][ty * 8];
            float4 a1 = *(const float4*)&As[k][ty * 8 + 4];
            float4 b0 = *(const float4*)&Bs[k][tx * 8];
            float4 b1 = *(const float4*)&Bs[k][tx * 8 + 4];
            float ar[8] = {a0.x, a0.y, a0.z, a0.w, a1.x, a1.y, a1.z, a1.w};
            float br[8] = {b0.x, b0.y, b0.z, b0.w, b1.x, b1.y, b1.z, b1.w};
#pragma unroll
            for (int i = 0; i < 8; i++)
#pragma unroll
                for (int j = 0; j < 8; j++) acc[i][j] += ar[i] * br[j];
        }
        __syncthreads();
    }

    int ncol = bn + tx * 8;
    float4 bb0 = *(const float4*)(bias + ncol);
    float4 bb1 = *(const float4*)(bias + ncol + 4);
#pragma unroll
    for (int i = 0; i < 8; i++) {
        int m = bm + ty * 8 + i;
        if (m >= M) continue;
        float* crow = C + (size_t)m * N + ncol;
        float4 v0 = make_float4(acc[i][0] + bb0.x, acc[i][1] + bb0.y,
                                acc[i][2] + bb0.z, acc[i][3] + bb0.w);
        float4 v1 = make_float4(acc[i][4] + bb1.x, acc[i][5] + bb1.y,
                                acc[i][6] + bb1.z, acc[i][7] + bb1.w);
        *(float4*)(crow) = v0;
        *(float4*)(crow + 4) = v1;
    }
}

// ---------------------------------------------------------------------------
// Software grid barrier. All NBLOCKS_GRU blocks must be co-resident
// (128 blocks, 1/SM, 148 SMs -> guaranteed).
// ---------------------------------------------------------------------------
__device__ __forceinline__ void grid_barrier() {
    __threadfence();          // make this thread's global writes visible
    __syncthreads();          // all block writes done & block-visible
    if (threadIdx.x == 0) {
        volatile unsigned int* vgen = &g_bar_gen;
        unsigned int gen = *vgen;
        __threadfence();
        if (atomicAdd(&g_bar_count, 1) == NBLOCKS_GRU - 1) {
            g_bar_count = 0;
            __threadfence();
            atomicAdd(&g_bar_gen, 1);
        } else {
            while (*vgen == gen) { }
            __threadfence();
        }
    }
    __syncthreads();
}

// ---------------------------------------------------------------------------
// Persistent GRU layer: runs all nsteps timesteps internally.
// grid = 128 blocks x 256 threads. Block bx owns n-columns [bx*4, bx*4+4)
// i.e. Whh rows {g*512 + bx*4 + nl : g in 0..2, nl in 0..3} (kept in SMEM).
//
// Per step:
//  - grid_barrier (prev step's h fully written)
//  - stage h[32][512] into SMEM
//  - warp w = (bgrp = w>>1, ngrp = w&1): 8 batches x 2 n x 3 gates tile,
//    lane = k-slice (k = lane + 32*i, 16 iters)  -> conflict-free LDS
//  - partials to SMEM (row pitch 385 -> conflict-free), reduce over 32 lanes
//  - threads 0..127 (one per (b, nl)) do gate math, write h_next and y
// Dynamic SMEM: hs 64KB + ws 24KB + P 48.1KB = 139392 B
// ---------------------------------------------------------------------------
#define P_PITCH 385

__global__ void __launch_bounds__(256)
gru_persistent(const float* __restrict__ gi,   // [nsteps][B][3H]
               const float* __restrict__ Whh,  // [3H][H]
               const float* __restrict__ bhh,  // [3H]
               float* __restrict__ hbuf0,      // initial h here
               float* __restrict__ hbuf1,
               float* __restrict__ y,          // [nsteps][B][H]
               int nsteps) {
    extern __shared__ float smem[];
    float* hs = smem;                 // [32][512]
    float* ws = hs + 32 * 512;        // [12][512]
    float* P  = ws + 12 * 512;        // [32][P_PITCH]

    int tid = threadIdx.x;
    int bx = blockIdx.x;
    int lane = tid & 31;
    int warp = tid >> 5;
    int bgrp = warp >> 1;             // 0..3
    int ngrp = warp & 1;              // 0..1
    int b0 = bgrp * 8;
    int nlb = ngrp * 2;

    // stage Whh slice once
    for (int i = tid; i < 12 * 512; i += 256) {
        int r = i >> 9, k = i & 511;
        int g = r >> 2, nl = r & 3;
        ws[r * 512 + k] = Whh[((size_t)(g * 512 + bx * 4 + nl)) * 512 + k];
    }

    // gate-thread constants (threads 0..127: one (b, nl) each)
    int gb = tid >> 2, gnl = tid & 3;
    int gn = bx * 4 + gnl;
    float bh_r = 0.f, bh_z = 0.f, bh_n = 0.f;
    if (tid < 128) {
        bh_r = bhh[gn];
        bh_z = bhh[512 + gn];
        bh_n = bhh[1024 + gn];
    }

    for (int t = 0; t < nsteps; t++) {
        const float* hcur = (t & 1) ? hbuf1 : hbuf0;
        float* hnext      = (t & 1) ? hbuf0 : hbuf1;

        grid_barrier();

        // stage h: 16384 floats = 4096 float4
        {
            const float4* src = (const float4*)hcur;
            float4* dst = (float4*)hs;
            for (int i = tid; i < (32 * 512) / 4; i += 256) dst[i] = src[i];
        }
        __syncthreads();

        float acc[8][6];
#pragma unroll
        for (int bb = 0; bb < 8; bb++)
#pragma unroll
            for (int q = 0; q < 6; q++) acc[bb][q] = 0.0f;

#pragma unroll
        for (int i = 0; i < 16; i++) {
            int k = lane + (i << 5);
            float wv[6];
#pragma unroll
            for (int g = 0; g < 3; g++)
#pragma unroll
                for (int j = 0; j < 2; j++)
                    wv[g * 2 + j] = ws[(g * 4 + nlb + j) * 512 + k];
            float hv[8];
#pragma unroll
            for (int bb = 0; bb < 8; bb++) hv[bb] = hs[(b0 + bb) * 512 + k];
#pragma unroll
            for (int bb = 0; bb < 8; bb++)
#pragma unroll
                for (int q = 0; q < 6; q++) acc[bb][q] += hv[bb] * wv[q];
        }

        // write partials: o = b*12 + g*4 + nl
#pragma unroll
        for (int bb = 0; bb < 8; bb++)
#pragma unroll
            for (int g = 0; g < 3; g++)
#pragma unroll
                for (int j = 0; j < 2; j++)
                    P[lane * P_PITCH + (b0 + bb) * 12 + g * 4 + nlb + j] =
                        acc[bb][g * 2 + j];
        __syncthreads();

        if (tid < 128) {
            int ob = gb * 12 + gnl;
            float sr = 0.f, sz = 0.f, sn = 0.f;
#pragma unroll
            for (int ks = 0; ks < 32; ks++) {
                sr += P[ks * P_PITCH + ob];
                sz += P[ks * P_PITCH + ob + 4];
                sn += P[ks * P_PITCH + ob + 8];
            }
            const float* gir = gi + (size_t)t * BATCH * G3H + (size_t)gb * G3H;
            float ir  = gir[gn];
            float iz  = gir[512 + gn];
            float inn = gir[1024 + gn];
            float hr = sr + bh_r, hz = sz + bh_z, hn = sn + bh_n;
            float rg = 1.0f / (1.0f + expf(-(ir + hr)));
            float zg = 1.0f / (1.0f + expf(-(iz + hz)));
            float cand = tanhf(inn + rg * hn);
            float hprev = hs[gb * 512 + gn];
            float hnew = (1.0f - zg) * cand + zg * hprev;
            hnext[gb * 512 + gn] = hnew;
            y[(size_t)t * BATCH * HDIM + (size_t)gb * HDIM + gn] = hnew;
        }
        // next iteration's grid_barrier provides the block sync before hs reuse
    }
}

// ---------------------------------------------------------------------------
extern "C" void kernel_launch(void* const* d_in, const int* in_sizes, int n_in,
                              void* d_out, int out_size) {
    const int*   src      = (const int*)d_in[0];
    const int*   trg      = (const int*)d_in[1];
    const float* enc_emb  = (const float*)d_in[2];
    const float* enc_Wih0 = (const float*)d_in[3];
    const float* enc_Whh0 = (const float*)d_in[4];
    const float* enc_bih0 = (const float*)d_in[5];
    const float* enc_bhh0 = (const float*)d_in[6];
    const float* enc_Wih1 = (const float*)d_in[7];
    const float* enc_Whh1 = (const float*)d_in[8];
    const float* enc_bih1 = (const float*)d_in[9];
    const float* enc_bhh1 = (const float*)d_in[10];
    const float* dec_emb  = (const float*)d_in[11];
    const float* dec_Wih0 = (const float*)d_in[12];
    const float* dec_Whh0 = (const float*)d_in[13];
    const float* dec_bih0 = (const float*)d_in[14];
    const float* dec_bhh0 = (const float*)d_in[15];
    const float* dec_Wih1 = (const float*)d_in[16];
    const float* dec_Whh1 = (const float*)d_in[17];
    const float* dec_bih1 = (const float*)d_in[18];
    const float* dec_bhh1 = (const float*)d_in[19];
    const float* out_W    = (const float*)d_in[20];
    const float* out_b    = (const float*)d_in[21];
    float* out = (float*)d_out;

    float *x, *gi, *seq0, *seq1, *hA0, *hB0, *hA1, *hB1;
    cudaGetSymbolAddress((void**)&x,    g_x);
    cudaGetSymbolAddress((void**)&gi,   g_gi);
    cudaGetSymbolAddress((void**)&seq0, g_seq0);
    cudaGetSymbolAddress((void**)&seq1, g_seq1);
    cudaGetSymbolAddress((void**)&hA0,  g_hA0);
    cudaGetSymbolAddress((void**)&hB0,  g_hB0);
    cudaGetSymbolAddress((void**)&hA1,  g_hA1);
    cudaGetSymbolAddress((void**)&hB1,  g_hB1);

    const int GRU_SMEM = (32 * 512 + 12 * 512 + 32 * P_PITCH) * 4; // 139392
    cudaFuncSetAttribute(gru_persistent,
                         cudaFuncAttributeMaxDynamicSharedMemorySize, GRU_SMEM);

    const int HB = BATCH * HDIM;

    // ---- Encoder ----
    embed_kernel<<<ENC_TOK, 128>>>(src, enc_emb, x, ENC_TOK);
    zero_kernel<<<(HB + 255) / 256, 256>>>(hA0, HB);
    zero_kernel<<<(HB + 255) / 256, 256>>>(hA1, HB);

    sgemm_bias<<<dim3(G3H / 128, (ENC_TOK + 127) / 128), 256>>>(
        x, enc_Wih0, enc_bih0, gi, ENC_TOK, G3H, EDIM);
    gru_persistent<<<NBLOCKS_GRU, 256, GRU_SMEM>>>(
        gi, enc_Whh0, enc_bhh0, hA0, hB0, seq0, S_LEN);
    // S_LEN=64 even -> final enc0 state in hA0

    sgemm_bias<<<dim3(G3H / 128, (ENC_TOK + 127) / 128), 256>>>(
        seq0, enc_Wih1, enc_bih1, gi, ENC_TOK, G3H, HDIM);
    gru_persistent<<<NBLOCKS_GRU, 256, GRU_SMEM>>>(
        gi, enc_Whh1, enc_bhh1, hA1, hB1, seq1, S_LEN);
    // final enc1 state in hA1

    // ---- Decoder ----
    embed_kernel<<<DEC_TOK, 128>>>(trg, dec_emb, x, DEC_TOK);

    sgemm_bias<<<dim3(G3H / 128, (DEC_TOK + 127) / 128), 256>>>(
        x, dec_Wih0, dec_bih0, gi, DEC_TOK, G3H, EDIM);
    gru_persistent<<<NBLOCKS_GRU, 256, GRU_SMEM>>>(
        gi, dec_Whh0, dec_bhh0, hA0, hB0, seq0, T_LEN - 1);

    sgemm_bias<<<dim3(G3H / 128, (DEC_TOK + 127) / 128), 256>>>(
        seq0, dec_Wih1, dec_bih1, gi, DEC_TOK, G3H, HDIM);
    gru_persistent<<<NBLOCKS_GRU, 256, GRU_SMEM>>>(
        gi, dec_Whh1, dec_bhh1, hA1, hB1, seq1, T_LEN - 1);

    // ---- Output projection ----
    sgemm_bias<<<dim3(VOCAB / 128, (DEC_TOK + 127) / 128), 256>>>(
        seq1, out_W, out_b, out, DEC_TOK, VOCAB, HDIM);
}

// round 3
// speedup vs baseline: 3.3678x; 1.3756x over previous
#include <cuda_runtime.h>
#include <cuda_bf16.h>
#include <math.h>
#include <stdint.h>

// Problem constants
#define S_LEN 64
#define T_LEN 48
#define BATCH 32
#define VOCAB 32000
#define EDIM 512
#define HDIM 512
#define G3H (3 * HDIM)                 // 1536
#define ENC_TOK (S_LEN * BATCH)        // 2048
#define DEC_TOK ((T_LEN - 1) * BATCH)  // 1504
#define DEC_PAD 1536                   // padded M for decoder-side GEMMs

#define NBLOCKS_GRU 128

// ---------------------------------------------------------------------------
// Scratch (device globals; no runtime allocation allowed)
// ---------------------------------------------------------------------------
__device__ float g_x[ENC_TOK * EDIM];
__device__ float g_gi[ENC_TOK * G3H];
__device__ float g_seq0[ENC_TOK * HDIM];
__device__ float g_seq1[ENC_TOK * HDIM];
__device__ float g_hA0[BATCH * HDIM];
__device__ float g_hB0[BATCH * HDIM];
__device__ float g_hA1[BATCH * HDIM];
__device__ float g_hB1[BATCH * HDIM];

// bf16 split scratch
__device__ __align__(16) __nv_bfloat16 g_Ahi[ENC_TOK * HDIM];
__device__ __align__(16) __nv_bfloat16 g_Alo[ENC_TOK * HDIM];
__device__ __align__(16) __nv_bfloat16 g_Whi[VOCAB * HDIM];
__device__ __align__(16) __nv_bfloat16 g_Wlo[VOCAB * HDIM];

// software grid barrier state
__device__ unsigned int g_bar_count = 0;
__device__ unsigned int g_bar_gen = 0;

// ---------------------------------------------------------------------------
__global__ void embed_kernel(const int* __restrict__ idx,
                             const float* __restrict__ emb,
                             float* __restrict__ out, int ntok) {
    int t = blockIdx.x;
    if (t >= ntok) return;
    int token = idx[t];
    const float4* src = (const float4*)(emb + (size_t)token * EDIM);
    float4* dst = (float4*)(out + (size_t)t * EDIM);
    dst[threadIdx.x] = src[threadIdx.x];
}

__global__ void zero_kernel(float* __restrict__ p, int n) {
    int i = blockIdx.x * blockDim.x + threadIdx.x;
    if (i < n) p[i] = 0.0f;
}

// ---------------------------------------------------------------------------
// Split fp32 -> (hi, lo) bf16.  For i in [n, npad): writes zeros.
// ---------------------------------------------------------------------------
__global__ void split_bf16_kernel(const float* __restrict__ x,
                                  __nv_bfloat16* __restrict__ hi,
                                  __nv_bfloat16* __restrict__ lo,
                                  int n, int npad) {
    int i = (blockIdx.x * blockDim.x + threadIdx.x) * 4;
    if (i >= npad) return;
    unsigned short hu[4], lu[4];
#pragma unroll
    for (int j = 0; j < 4; j++) {
        float v = (i + j < n) ? x[i + j] : 0.0f;
        __nv_bfloat16 h = __float2bfloat16(v);
        __nv_bfloat16 l = __float2bfloat16(v - __bfloat162float(h));
        hu[j] = __bfloat16_as_ushort(h);
        lu[j] = __bfloat16_as_ushort(l);
    }
    uint2 hp, lp;
    hp.x = (uint32_t)hu[0] | ((uint32_t)hu[1] << 16);
    hp.y = (uint32_t)hu[2] | ((uint32_t)hu[3] << 16);
    lp.x = (uint32_t)lu[0] | ((uint32_t)lu[1] << 16);
    lp.y = (uint32_t)lu[2] | ((uint32_t)lu[3] << 16);
    *(uint2*)(hi + i) = hp;
    *(uint2*)(lo + i) = lp;
}

// ---------------------------------------------------------------------------
// Tensor-core GEMM with split-bf16 inputs:
//   C[M,N] = (Ahi+Alo)[M,K] @ (Whi+Wlo)[N,K]^T + bias[N]   (lo*lo dropped)
// 256 threads, block tile 128x128, BK=64, warp grid 2(m) x 4(n),
// warp tile 64x32 -> 4 m-frags x 4 n-frags of m16n8k16.
// A buffers must be padded to a multiple of 128 rows; store guarded by M.
// N % 128 == 0, K % 64 == 0.
// ---------------------------------------------------------------------------
#define GP 72   // smem row pitch in bf16 elems (144 B -> conflict-free ldmatrix)

__device__ __forceinline__ uint32_t s2u(const void* p) {
    return (uint32_t)__cvta_generic_to_shared(p);
}

__device__ __forceinline__ void ldm_x4(uint32_t* r, uint32_t addr) {
    asm volatile("ldmatrix.sync.aligned.m8n8.x4.shared.b16 {%0,%1,%2,%3}, [%4];\n"
                 : "=r"(r[0]), "=r"(r[1]), "=r"(r[2]), "=r"(r[3]) : "r"(addr));
}
__device__ __forceinline__ void ldm_x2(uint32_t* r, uint32_t addr) {
    asm volatile("ldmatrix.sync.aligned.m8n8.x2.shared.b16 {%0,%1}, [%2];\n"
                 : "=r"(r[0]), "=r"(r[1]) : "r"(addr));
}
__device__ __forceinline__ void mma16816(float* c, const uint32_t* a,
                                         const uint32_t* b) {
    asm volatile(
        "mma.sync.aligned.m16n8k16.row.col.f32.bf16.bf16.f32 "
        "{%0,%1,%2,%3}, {%4,%5,%6,%7}, {%8,%9}, {%0,%1,%2,%3};\n"
        : "+f"(c[0]), "+f"(c[1]), "+f"(c[2]), "+f"(c[3])
        : "r"(a[0]), "r"(a[1]), "r"(a[2]), "r"(a[3]), "r"(b[0]), "r"(b[1]));
}

__global__ void __launch_bounds__(256)
gemm_bf16split(const __nv_bfloat16* __restrict__ Ahi,
               const __nv_bfloat16* __restrict__ Alo,
               const __nv_bfloat16* __restrict__ Whi,
               const __nv_bfloat16* __restrict__ Wlo,
               const float* __restrict__ bias,
               float* __restrict__ C,
               int M, int N, int K) {
    extern __shared__ unsigned char dynsmem[];
    __nv_bfloat16* sAhi = (__nv_bfloat16*)dynsmem;          // [128][GP]
    __nv_bfloat16* sAlo = sAhi + 128 * GP;
    __nv_bfloat16* sWhi = sAlo + 128 * GP;
    __nv_bfloat16* sWlo = sWhi + 128 * GP;

    int tid = threadIdx.x;
    int lane = tid & 31, warp = tid >> 5;
    int wm = warp >> 2;        // 0..1
    int wn = warp & 3;         // 0..3
    int bm = blockIdx.y * 128, bn = blockIdx.x * 128;

    float acc[4][4][4];
#pragma unroll
    for (int mi = 0; mi < 4; mi++)
#pragma unroll
        for (int ni = 0; ni < 4; ni++)
#pragma unroll
            for (int e = 0; e < 4; e++) acc[mi][ni][e] = 0.0f;

    for (int k0 = 0; k0 < K; k0 += 64) {
        // stage 128x64 tiles of all four matrices (uint4 = 8 bf16)
#pragma unroll
        for (int i = tid; i < 1024; i += 256) {
            int r = i >> 3, s = i & 7;
            size_t goffA = (size_t)(bm + r) * K + k0 + s * 8;
            size_t goffW = (size_t)(bn + r) * K + k0 + s * 8;
            *(uint4*)&sAhi[r * GP + s * 8] = *(const uint4*)(Ahi + goffA);
            *(uint4*)&sAlo[r * GP + s * 8] = *(const uint4*)(Alo + goffA);
            *(uint4*)&sWhi[r * GP + s * 8] = *(const uint4*)(Whi + goffW);
            *(uint4*)&sWlo[r * GP + s * 8] = *(const uint4*)(Wlo + goffW);
        }
        __syncthreads();

#pragma unroll
        for (int ks = 0; ks < 4; ks++) {
            int arow = wm * 64 + (lane & 15);
            int acol = ks * 16 + (lane >> 4) * 8;
            uint32_t ahi[4][4], alo[4][4];
#pragma unroll
            for (int mi = 0; mi < 4; mi++) {
                ldm_x4(ahi[mi], s2u(&sAhi[(arow + mi * 16) * GP + acol]));
                ldm_x4(alo[mi], s2u(&sAlo[(arow + mi * 16) * GP + acol]));
            }
            int brow = wn * 32 + (lane & 7);
            int bcol = ks * 16 + ((lane >> 3) & 1) * 8;
            uint32_t bhi[4][2], blo[4][2];
#pragma unroll
            for (int ni = 0; ni < 4; ni++) {
                ldm_x2(bhi[ni], s2u(&sWhi[(brow + ni * 8) * GP + bcol]));
                ldm_x2(blo[ni], s2u(&sWlo[(brow + ni * 8) * GP + bcol]));
            }
#pragma unroll
            for (int mi = 0; mi < 4; mi++)
#pragma unroll
                for (int ni = 0; ni < 4; ni++) {
                    mma16816(acc[mi][ni], ahi[mi], bhi[ni]);
                    mma16816(acc[mi][ni], ahi[mi], blo[ni]);
                    mma16816(acc[mi][ni], alo[mi], bhi[ni]);
                }
        }
        __syncthreads();
    }

    // epilogue
    int g = lane >> 2, q = lane & 3;
#pragma unroll
    for (int mi = 0; mi < 4; mi++) {
#pragma unroll
        for (int ni = 0; ni < 4; ni++) {
            int m0 = bm + wm * 64 + mi * 16 + g;
            int n0 = bn + wn * 32 + ni * 8 + q * 2;
            float b0 = bias[n0], b1 = bias[n0 + 1];
            if (m0 < M) {
                float2 v = make_float2(acc[mi][ni][0] + b0, acc[mi][ni][1] + b1);
                *(float2*)(C + (size_t)m0 * N + n0) = v;
            }
            if (m0 + 8 < M) {
                float2 v = make_float2(acc[mi][ni][2] + b0, acc[mi][ni][3] + b1);
                *(float2*)(C + (size_t)(m0 + 8) * N + n0) = v;
            }
        }
    }
}

// ---------------------------------------------------------------------------
// Software grid barrier (all NBLOCKS_GRU blocks co-resident).
// ---------------------------------------------------------------------------
__device__ __forceinline__ void grid_barrier() {
    __threadfence();
    __syncthreads();
    if (threadIdx.x == 0) {
        volatile unsigned int* vgen = &g_bar_gen;
        unsigned int gen = *vgen;
        __threadfence();
        if (atomicAdd(&g_bar_count, 1) == NBLOCKS_GRU - 1) {
            g_bar_count = 0;
            __threadfence();
            atomicAdd(&g_bar_gen, 1);
        } else {
            while (*vgen == gen) { }
            __threadfence();
        }
    }
    __syncthreads();
}

// ---------------------------------------------------------------------------
// Persistent GRU layer (unchanged from R2).
// ---------------------------------------------------------------------------
#define P_PITCH 385

__global__ void __launch_bounds__(256)
gru_persistent(const float* __restrict__ gi,   // [nsteps][B][3H]
               const float* __restrict__ Whh,  // [3H][H]
               const float* __restrict__ bhh,  // [3H]
               float* __restrict__ hbuf0,
               float* __restrict__ hbuf1,
               float* __restrict__ y,          // [nsteps][B][H]
               int nsteps) {
    extern __shared__ unsigned char dynsmem[];
    float* smemf = (float*)dynsmem;
    float* hs = smemf;                // [32][512]
    float* ws = hs + 32 * 512;        // [12][512]
    float* P  = ws + 12 * 512;        // [32][P_PITCH]

    int tid = threadIdx.x;
    int bx = blockIdx.x;
    int lane = tid & 31;
    int warp = tid >> 5;
    int bgrp = warp >> 1;
    int ngrp = warp & 1;
    int b0 = bgrp * 8;
    int nlb = ngrp * 2;

    for (int i = tid; i < 12 * 512; i += 256) {
        int r = i >> 9, k = i & 511;
        int gte = r >> 2, nl = r & 3;
        ws[r * 512 + k] = Whh[((size_t)(gte * 512 + bx * 4 + nl)) * 512 + k];
    }

    int gb = tid >> 2, gnl = tid & 3;
    int gn = bx * 4 + gnl;
    float bh_r = 0.f, bh_z = 0.f, bh_n = 0.f;
    if (tid < 128) {
        bh_r = bhh[gn];
        bh_z = bhh[512 + gn];
        bh_n = bhh[1024 + gn];
    }

    for (int t = 0; t < nsteps; t++) {
        const float* hcur = (t & 1) ? hbuf1 : hbuf0;
        float* hnext      = (t & 1) ? hbuf0 : hbuf1;

        grid_barrier();

        {
            const float4* src = (const float4*)hcur;
            float4* dst = (float4*)hs;
            for (int i = tid; i < (32 * 512) / 4; i += 256) dst[i] = src[i];
        }
        __syncthreads();

        float acc[8][6];
#pragma unroll
        for (int bb = 0; bb < 8; bb++)
#pragma unroll
            for (int qq = 0; qq < 6; qq++) acc[bb][qq] = 0.0f;

#pragma unroll
        for (int i = 0; i < 16; i++) {
            int k = lane + (i << 5);
            float wv[6];
#pragma unroll
            for (int gte = 0; gte < 3; gte++)
#pragma unroll
                for (int j = 0; j < 2; j++)
                    wv[gte * 2 + j] = ws[(gte * 4 + nlb + j) * 512 + k];
            float hv[8];
#pragma unroll
            for (int bb = 0; bb < 8; bb++) hv[bb] = hs[(b0 + bb) * 512 + k];
#pragma unroll
            for (int bb = 0; bb < 8; bb++)
#pragma unroll
                for (int qq = 0; qq < 6; qq++) acc[bb][qq] += hv[bb] * wv[qq];
        }

#pragma unroll
        for (int bb = 0; bb < 8; bb++)
#pragma unroll
            for (int gte = 0; gte < 3; gte++)
#pragma unroll
                for (int j = 0; j < 2; j++)
                    P[lane * P_PITCH + (b0 + bb) * 12 + gte * 4 + nlb + j] =
                        acc[bb][gte * 2 + j];
        __syncthreads();

        if (tid < 128) {
            int ob = gb * 12 + gnl;
            float sr = 0.f, sz = 0.f, sn = 0.f;
#pragma unroll
            for (int ks = 0; ks < 32; ks++) {
                sr += P[ks * P_PITCH + ob];
                sz += P[ks * P_PITCH + ob + 4];
                sn += P[ks * P_PITCH + ob + 8];
            }
            const float* gir = gi + (size_t)t * BATCH * G3H + (size_t)gb * G3H;
            float ir  = gir[gn];
            float iz  = gir[512 + gn];
            float inn = gir[1024 + gn];
            float hr = sr + bh_r, hz = sz + bh_z, hn = sn + bh_n;
            float rg = 1.0f / (1.0f + expf(-(ir + hr)));
            float zg = 1.0f / (1.0f + expf(-(iz + hz)));
            float cand = tanhf(inn + rg * hn);
            float hprev = hs[gb * 512 + gn];
            float hnew = (1.0f - zg) * cand + zg * hprev;
            hnext[gb * 512 + gn] = hnew;
            y[(size_t)t * BATCH * HDIM + (size_t)gb * HDIM + gn] = hnew;
        }
    }
}

// ---------------------------------------------------------------------------
static inline void split_to(const float* x, __nv_bfloat16* hi, __nv_bfloat16* lo,
                            int n, int npad) {
    int thr = (npad / 4 + 255) / 256;
    split_bf16_kernel<<<thr, 256>>>(x, hi, lo, n, npad);
}

extern "C" void kernel_launch(void* const* d_in, const int* in_sizes, int n_in,
                              void* d_out, int out_size) {
    const int*   src      = (const int*)d_in[0];
    const int*   trg      = (const int*)d_in[1];
    const float* enc_emb  = (const float*)d_in[2];
    const float* enc_Wih0 = (const float*)d_in[3];
    const float* enc_Whh0 = (const float*)d_in[4];
    const float* enc_bih0 = (const float*)d_in[5];
    const float* enc_bhh0 = (const float*)d_in[6];
    const float* enc_Wih1 = (const float*)d_in[7];
    const float* enc_Whh1 = (const float*)d_in[8];
    const float* enc_bih1 = (const float*)d_in[9];
    const float* enc_bhh1 = (const float*)d_in[10];
    const float* dec_emb  = (const float*)d_in[11];
    const float* dec_Wih0 = (const float*)d_in[12];
    const float* dec_Whh0 = (const float*)d_in[13];
    const float* dec_bih0 = (const float*)d_in[14];
    const float* dec_bhh0 = (const float*)d_in[15];
    const float* dec_Wih1 = (const float*)d_in[16];
    const float* dec_Whh1 = (const float*)d_in[17];
    const float* dec_bih1 = (const float*)d_in[18];
    const float* dec_bhh1 = (const float*)d_in[19];
    const float* out_W    = (const float*)d_in[20];
    const float* out_b    = (const float*)d_in[21];
    float* out = (float*)d_out;

    float *x, *gi, *seq0, *seq1, *hA0, *hB0, *hA1, *hB1;
    cudaGetSymbolAddress((void**)&x,    g_x);
    cudaGetSymbolAddress((void**)&gi,   g_gi);
    cudaGetSymbolAddress((void**)&seq0, g_seq0);
    cudaGetSymbolAddress((void**)&seq1, g_seq1);
    cudaGetSymbolAddress((void**)&hA0,  g_hA0);
    cudaGetSymbolAddress((void**)&hB0,  g_hB0);
    cudaGetSymbolAddress((void**)&hA1,  g_hA1);
    cudaGetSymbolAddress((void**)&hB1,  g_hB1);
    __nv_bfloat16 *Ahi, *Alo, *Whi, *Wlo;
    cudaGetSymbolAddress((void**)&Ahi, g_Ahi);
    cudaGetSymbolAddress((void**)&Alo, g_Alo);
    cudaGetSymbolAddress((void**)&Whi, g_Whi);
    cudaGetSymbolAddress((void**)&Wlo, g_Wlo);

    const int GRU_SMEM = (32 * 512 + 12 * 512 + 32 * P_PITCH) * 4;
    cudaFuncSetAttribute(gru_persistent,
                         cudaFuncAttributeMaxDynamicSharedMemorySize, GRU_SMEM);
    const int GEMM_SMEM = 4 * 128 * GP * 2;  // 73728
    cudaFuncSetAttribute(gemm_bf16split,
                         cudaFuncAttributeMaxDynamicSharedMemorySize, GEMM_SMEM);

    const int HB = BATCH * HDIM;

    // ---- Encoder ----
    embed_kernel<<<ENC_TOK, 128>>>(src, enc_emb, x, ENC_TOK);
    zero_kernel<<<(HB + 255) / 256, 256>>>(hA0, HB);
    zero_kernel<<<(HB + 255) / 256, 256>>>(hA1, HB);

    // enc layer 0
    split_to(x, Ahi, Alo, ENC_TOK * EDIM, ENC_TOK * EDIM);
    split_to(enc_Wih0, Whi, Wlo, G3H * EDIM, G3H * EDIM);
    gemm_bf16split<<<dim3(G3H / 128, ENC_TOK / 128), 256, GEMM_SMEM>>>(
        Ahi, Alo, Whi, Wlo, enc_bih0, gi, ENC_TOK, G3H, EDIM);
    gru_persistent<<<NBLOCKS_GRU, 256, GRU_SMEM>>>(
        gi, enc_Whh0, enc_bhh0, hA0, hB0, seq0, S_LEN);

    // enc layer 1
    split_to(seq0, Ahi, Alo, ENC_TOK * HDIM, ENC_TOK * HDIM);
    split_to(enc_Wih1, Whi, Wlo, G3H * HDIM, G3H * HDIM);
    gemm_bf16split<<<dim3(G3H / 128, ENC_TOK / 128), 256, GEMM_SMEM>>>(
        Ahi, Alo, Whi, Wlo, enc_bih1, gi, ENC_TOK, G3H, HDIM);
    gru_persistent<<<NBLOCKS_GRU, 256, GRU_SMEM>>>(
        gi, enc_Whh1, enc_bhh1, hA1, hB1, seq1, S_LEN);

    // ---- Decoder ----
    embed_kernel<<<DEC_TOK, 128>>>(trg, dec_emb, x, DEC_TOK);

    split_to(x, Ahi, Alo, DEC_TOK * EDIM, DEC_PAD * EDIM);
    split_to(dec_Wih0, Whi, Wlo, G3H * EDIM, G3H * EDIM);
    gemm_bf16split<<<dim3(G3H / 128, DEC_PAD / 128), 256, GEMM_SMEM>>>(
        Ahi, Alo, Whi, Wlo, dec_bih0, gi, DEC_PAD, G3H, EDIM);
    gru_persistent<<<NBLOCKS_GRU, 256, GRU_SMEM>>>(
        gi, dec_Whh0, dec_bhh0, hA0, hB0, seq0, T_LEN - 1);

    split_to(seq0, Ahi, Alo, DEC_TOK * HDIM, DEC_PAD * HDIM);
    split_to(dec_Wih1, Whi, Wlo, G3H * HDIM, G3H * HDIM);
    gemm_bf16split<<<dim3(G3H / 128, DEC_PAD / 128), 256, GEMM_SMEM>>>(
        Ahi, Alo, Whi, Wlo, dec_bih1, gi, DEC_PAD, G3H, HDIM);
    gru_persistent<<<NBLOCKS_GRU, 256, GRU_SMEM>>>(
        gi, dec_Whh1, dec_bhh1, hA1, hB1, seq1, T_LEN - 1);

    // ---- Output projection ----
    split_to(seq1, Ahi, Alo, DEC_TOK * HDIM, DEC_PAD * HDIM);
    split_to(out_W, Whi, Wlo, VOCAB * HDIM, VOCAB * HDIM);
    gemm_bf16split<<<dim3(VOCAB / 128, DEC_PAD / 128), 256, GEMM_SMEM>>>(
        Ahi, Alo, Whi, Wlo, out_b, out, DEC_TOK, VOCAB, HDIM);
}